// round 9
// baseline (speedup 1.0000x reference)
#include <cuda_runtime.h>
#include <cuda_fp16.h>
#include <cstdint>
#include <mma.h>
#include <math.h>

using namespace nvcuda;

#define S   512
#define T   16384
#define D   512
#define DFF 2048
#define SEG (T / S)          // 32 frames per segment
#define BAND 96              // 3*SEG frames per query band

// -------- scratch (allocation-free: __device__ globals) --------
__device__ __half g_rctx_h[S * D];            // relu(ctx) fp16
__device__ __half g_xh[S * D];                // x fp16 (GEMM A)
__device__ __half g_h[S * DFF];               // relu FFN hidden fp16
__device__ __half g_wh[D * D + DFF * D + D * DFF];  // fp16 weights
__device__ float  g_x[S * D];                 // x fp32 (residual)
__device__ float  g_part[4 * S * D];          // split-K partials
__device__ float  g_sc[S * BAND];             // raw scores

// ============================================================
// cp.async helpers
// ============================================================
__device__ __forceinline__ void cp_async16(void* sm, const void* gm) {
    unsigned int a = (unsigned int)__cvta_generic_to_shared(sm);
    asm volatile("cp.async.cg.shared.global [%0], [%1], 16;" :: "r"(a), "l"(gm) : "memory");
}
__device__ __forceinline__ void cp_commit() {
    asm volatile("cp.async.commit_group;" ::: "memory");
}
__device__ __forceinline__ void cp_wait1() {
    asm volatile("cp.async.wait_group 1;" ::: "memory");
}

// ============================================================
// Weight conversion fp32 -> fp16
// ============================================================
__global__ __launch_bounds__(256) void cvt_kernel(
    const float* __restrict__ w0, const float* __restrict__ w1,
    const float* __restrict__ w2)
{
    const int mat = blockIdx.y;
    const float2* src;
    __half2* dst;
    int n2;
    if (mat == 0) { src = (const float2*)w0; dst = (__half2*)g_wh;                 n2 = D * D / 2; }
    else if (mat == 1) { src = (const float2*)w1; dst = (__half2*)(g_wh + D * D);  n2 = DFF * D / 2; }
    else { src = (const float2*)w2; dst = (__half2*)(g_wh + D * D + DFF * D);      n2 = D * DFF / 2; }
    for (int i = blockIdx.x * 256 + threadIdx.x; i < n2; i += gridDim.x * 256)
        dst[i] = __float22half2_rn(src[i]);
}

// ============================================================
// Score kernel (frame-parallel, exactly-once streaming read).
// Block = 64 frames, 256 threads = 8 warps, 8 frames/warp in pairs.
// Each frame t (seg a) contributes scores to queries {a-1, a, a+1}.
// Score slot for query s: idx = t - (s-1)*SEG in [0, 96).
// ============================================================
__global__ __launch_bounds__(256) void score_kernel(
    const float* __restrict__ tgt, const float* __restrict__ mem,
    const float* __restrict__ pos, const float* __restrict__ qpos,
    const int*   __restrict__ aidx)
{
    const int tid  = threadIdx.x;
    const int warp = tid >> 5, lane = tid & 31;
    const int t0   = blockIdx.x * 64;
    const int a0   = t0 >> 5;            // frames span segs {a0, a0+1}
    const int qlo  = a0 - 1;             // queries qlo .. qlo+3

    __shared__ float4 qs[4][D / 4];

    // load the 4 (possibly clipped) query vectors q = tgt + qpos
    for (int i = tid; i < 4 * (D / 4); i += 256) {
        const int r = i >> 7, d4 = i & 127;
        const int s = qlo + r;
        float4 v = make_float4(0.f, 0.f, 0.f, 0.f);
        if ((unsigned)s < S) {
            float4 tv = ((const float4*)tgt)[(size_t)s * (D / 4) + d4];
            float4 pv = ((const float4*)qpos)[(size_t)s * (D / 4) + d4];
            v = make_float4(tv.x + pv.x, tv.y + pv.y, tv.z + pv.z, tv.w + pv.w);
        }
        qs[r][d4] = v;
    }
    __syncthreads();

    const float scale = 0.04419417382415922f;  // 1/sqrt(512)

    // warp handles frames [t0+8w, t0+8w+8), in pairs for ILP
    #pragma unroll
    for (int it = 0; it < 4; it++) {
        const int tA = t0 + warp * 8 + it * 2;
        const int tB = tA + 1;
        const float4* mA = (const float4*)mem + (size_t)tA * (D / 4);
        const float4* pA = (const float4*)pos + (size_t)tA * (D / 4);
        const float4* mB = (const float4*)mem + (size_t)tB * (D / 4);
        const float4* pB = (const float4*)pos + (size_t)tB * (D / 4);
        const int rA = (tA >> 5) - a0;   // 0 or 1
        const int rB = (tB >> 5) - a0;

        float dA[3] = {0.f, 0.f, 0.f};
        float dB[3] = {0.f, 0.f, 0.f};
        #pragma unroll
        for (int i = 0; i < 4; i++) {
            const int d4 = lane + 32 * i;
            float4 ma = mA[d4], pa = pA[d4];
            float4 mb = mB[d4], pb = pB[d4];
            float4 kA = make_float4(ma.x + pa.x, ma.y + pa.y, ma.z + pa.z, ma.w + pa.w);
            float4 kB = make_float4(mb.x + pb.x, mb.y + pb.y, mb.z + pb.z, mb.w + pb.w);
            #pragma unroll
            for (int e = 0; e < 3; e++) {
                float4 qa = qs[rA + e][d4];
                float4 qb = qs[rB + e][d4];
                dA[e] = fmaf(kA.x, qa.x, fmaf(kA.y, qa.y, fmaf(kA.z, qa.z, fmaf(kA.w, qa.w, dA[e]))));
                dB[e] = fmaf(kB.x, qb.x, fmaf(kB.y, qb.y, fmaf(kB.z, qb.z, fmaf(kB.w, qb.w, dB[e]))));
            }
        }
        #pragma unroll
        for (int o = 16; o > 0; o >>= 1) {
            #pragma unroll
            for (int e = 0; e < 3; e++) {
                dA[e] += __shfl_xor_sync(0xffffffffu, dA[e], o);
                dB[e] += __shfl_xor_sync(0xffffffffu, dB[e], o);
            }
        }
        // lanes 0..2 write frame A's entries; lanes 3..5 frame B's
        if (lane < 6) {
            const bool isB = lane >= 3;
            const int  e   = isB ? lane - 3 : lane;
            const int  t   = isB ? tB : tA;
            const int  a   = (t >> 5);
            const int  sq  = a - 1 + e;            // target query
            if ((unsigned)sq < S) {
                const int idx = t - (sq - 1) * SEG; // in [0,96)
                const float v = (isB ? dB[e] : dA[e]) * scale;
                g_sc[sq * BAND + idx] = v;
            }
        }
    }
}

// ============================================================
// Fused softmax + ctx kernel. One block (128 thr) per query.
// Band frames: t = (s-1)*SEG + f, f in [lo, hi).
// ============================================================
__global__ __launch_bounds__(128) void ctx_kernel(
    const float* __restrict__ mem)
{
    const int s    = blockIdx.x;
    const int tid  = threadIdx.x;
    const int warp = tid >> 5, lane = tid & 31;

    __shared__ float p[BAND];
    __shared__ float sraw[BAND];
    __shared__ float inv_s;

    const int lo = (s == 0) ? SEG : 0;
    const int hi = (s == S - 1) ? 2 * SEG : BAND;

    if (tid < BAND) sraw[tid] = g_sc[s * BAND + tid];
    __syncthreads();

    if (warp == 0) {
        float v[3];
        #pragma unroll
        for (int j = 0; j < 3; j++) {
            const int f = lane + 32 * j;
            v[j] = (f >= lo && f < hi) ? sraw[f] : -INFINITY;
        }
        float m = fmaxf(v[0], fmaxf(v[1], v[2]));
        #pragma unroll
        for (int o = 16; o > 0; o >>= 1)
            m = fmaxf(m, __shfl_xor_sync(0xffffffffu, m, o));
        float e[3], ssum = 0.f;
        #pragma unroll
        for (int j = 0; j < 3; j++) {
            e[j] = __expf(v[j] - m);          // exp(-inf) = 0 for masked
            ssum += e[j];
        }
        #pragma unroll
        for (int o = 16; o > 0; o >>= 1)
            ssum += __shfl_xor_sync(0xffffffffu, ssum, o);
        #pragma unroll
        for (int j = 0; j < 3; j++) p[lane + 32 * j] = e[j];
        if (lane == 0) inv_s = 1.f / ssum;
    }
    __syncthreads();

    const float inv = inv_s;
    const int tbase = (s - 1) * SEG;
    const float4* m4 = (const float4*)mem;
    float4 acc = make_float4(0.f, 0.f, 0.f, 0.f);
    #pragma unroll 4
    for (int f = lo; f < hi; f++) {
        const float pw = p[f];
        float4 mv = m4[(size_t)(tbase + f) * (D / 4) + tid];
        acc.x = fmaf(pw, mv.x, acc.x);
        acc.y = fmaf(pw, mv.y, acc.y);
        acc.z = fmaf(pw, mv.z, acc.z);
        acc.w = fmaf(pw, mv.w, acc.w);
    }
    acc.x = fmaxf(acc.x * inv, 0.f);
    acc.y = fmaxf(acc.y * inv, 0.f);
    acc.z = fmaxf(acc.z * inv, 0.f);
    acc.w = fmaxf(acc.w * inv, 0.f);
    __half2* outp = (__half2*)g_rctx_h + (size_t)s * (D / 2) + tid * 2;
    outp[0] = __floats2half2_rn(acc.x, acc.y);
    outp[1] = __floats2half2_rn(acc.z, acc.w);
}

// ============================================================
// FP16 tensor-core GEMM, double-buffered cp.async.
// BM=BN=64, BK=64, 128 threads (4 warps, 32x32 warp tiles).
// MODE 0: fp32 raw partials to ((float*)C) + z*M*N
// MODE 1: relu(acc + bias) -> fp16 to (half*)C
// ============================================================
template <int KSPLIT, int MODE>
__global__ __launch_bounds__(128) void gemm_h(
    const __half* __restrict__ A, const __half* __restrict__ W,
    const float* __restrict__ bias, void* __restrict__ C,
    int M, int N, int K)
{
    constexpr int BM = 64, BN = 64, BK = 64;
    constexpr int LDA = BK + 8;
    constexpr int LDC = BN + 4;

    __shared__ union SmemU {
        struct { __half A[2][BM][LDA]; __half B[2][BN][LDA]; } s;
        float Cs[BM][LDC];
    } sm;

    const int tid  = threadIdx.x;
    const int warp = tid >> 5;
    const int wm = warp >> 1, wn = warp & 1;
    const int col0 = blockIdx.x * BN;
    const int row0 = blockIdx.y * BM;
    const int Kloc = K / KSPLIT;
    const int kbase = blockIdx.z * Kloc;

    wmma::fragment<wmma::accumulator, 16, 16, 16, float> acc[2][2];
    #pragma unroll
    for (int i = 0; i < 2; i++)
        #pragma unroll
        for (int j = 0; j < 2; j++)
            wmma::fill_fragment(acc[i][j], 0.f);

    const int NIT = Kloc / BK;

    auto load_tile = [&](int it, int st) {
        const int k0 = kbase + it * BK;
        #pragma unroll
        for (int i = tid; i < BM * (BK / 8); i += 128) {
            int r = i >> 3, c = (i & 7) * 8;
            cp_async16(&sm.s.A[st][r][c], &A[(size_t)(row0 + r) * K + k0 + c]);
        }
        #pragma unroll
        for (int i = tid; i < BN * (BK / 8); i += 128) {
            int r = i >> 3, c = (i & 7) * 8;
            cp_async16(&sm.s.B[st][r][c], &W[(size_t)(col0 + r) * K + k0 + c]);
        }
    };

    load_tile(0, 0);
    cp_commit();

    for (int it = 0; it < NIT; it++) {
        if (it + 1 < NIT) load_tile(it + 1, (it + 1) & 1);
        cp_commit();
        cp_wait1();
        __syncthreads();

        const int st = it & 1;
        #pragma unroll
        for (int kk = 0; kk < BK; kk += 16) {
            wmma::fragment<wmma::matrix_a, 16, 16, 16, __half, wmma::row_major> fa[2];
            wmma::fragment<wmma::matrix_b, 16, 16, 16, __half, wmma::col_major> fb[2];
            #pragma unroll
            for (int i = 0; i < 2; i++)
                wmma::load_matrix_sync(fa[i], &sm.s.A[st][wm * 32 + i * 16][kk], LDA);
            #pragma unroll
            for (int j = 0; j < 2; j++)
                wmma::load_matrix_sync(fb[j], &sm.s.B[st][wn * 32 + j * 16][kk], LDA);
            #pragma unroll
            for (int i = 0; i < 2; i++)
                #pragma unroll
                for (int j = 0; j < 2; j++)
                    wmma::mma_sync(acc[i][j], fa[i], fb[j], acc[i][j]);
        }
        __syncthreads();
    }

    #pragma unroll
    for (int i = 0; i < 2; i++)
        #pragma unroll
        for (int j = 0; j < 2; j++)
            wmma::store_matrix_sync(&sm.Cs[wm * 32 + i * 16][wn * 32 + j * 16],
                                    acc[i][j], LDC, wmma::mem_row_major);
    __syncthreads();

    if (MODE == 0) {
        float* Co = (float*)C + (size_t)blockIdx.z * M * N;
        #pragma unroll
        for (int i = tid; i < BM * (BN / 4); i += 128) {
            int r = i / (BN / 4), c = (i % (BN / 4)) * 4;
            float4 v = *(float4*)&sm.Cs[r][c];
            *(float4*)&Co[(size_t)(row0 + r) * N + col0 + c] = v;
        }
    } else {
        __half* Co = (__half*)C;
        #pragma unroll
        for (int i = tid; i < BM * (BN / 4); i += 128) {
            int r = i / (BN / 4), c = (i % (BN / 4)) * 4;
            float4 v = *(float4*)&sm.Cs[r][c];
            float4 b4 = *(const float4*)&bias[col0 + c];
            v.x = fmaxf(v.x + b4.x, 0.f);
            v.y = fmaxf(v.y + b4.y, 0.f);
            v.z = fmaxf(v.z + b4.z, 0.f);
            v.w = fmaxf(v.w + b4.w, 0.f);
            __half2* o2 = (__half2*)&Co[(size_t)(row0 + r) * N + col0 + c];
            o2[0] = __floats2half2_rn(v.x, v.y);
            o2[1] = __floats2half2_rn(v.z, v.w);
        }
    }
}

// ============================================================
// LayerNorm, vectorized, single reduction round (sum, sumsq).
// v = sum_k parts[k] + res + bias; out = LN(v)*g + be.
// WH: also write fp16 x to g_xh.
// ============================================================
template <int NP, bool WH>
__global__ __launch_bounds__(128) void ln_kernel(
    const float* __restrict__ parts,
    const float* __restrict__ bias, const float* __restrict__ res,
    const float* __restrict__ g, const float* __restrict__ be,
    float* __restrict__ out)
{
    const int row = blockIdx.x;
    const int tid = threadIdx.x;           // 0..127, one float4 each
    const size_t base = (size_t)row * (D / 4);

    float4 v = ((const float4*)res)[base + tid];
    {
        float4 b4 = ((const float4*)bias)[tid];
        v.x += b4.x; v.y += b4.y; v.z += b4.z; v.w += b4.w;
    }
    #pragma unroll
    for (int k = 0; k < NP; k++) {
        float4 pv = ((const float4*)parts)[(size_t)k * S * (D / 4) + base + tid];
        v.x += pv.x; v.y += pv.y; v.z += pv.z; v.w += pv.w;
    }

    float s1 = v.x + v.y + v.z + v.w;
    float s2 = v.x * v.x + v.y * v.y + v.z * v.z + v.w * v.w;

    __shared__ float r1[4], r2[4];
    __shared__ float mu_s, rstd_s;
    #pragma unroll
    for (int o = 16; o > 0; o >>= 1) {
        s1 += __shfl_xor_sync(0xffffffffu, s1, o);
        s2 += __shfl_xor_sync(0xffffffffu, s2, o);
    }
    if ((tid & 31) == 0) { r1[tid >> 5] = s1; r2[tid >> 5] = s2; }
    __syncthreads();
    if (tid == 0) {
        float t1 = r1[0] + r1[1] + r1[2] + r1[3];
        float t2 = r2[0] + r2[1] + r2[2] + r2[3];
        const float mu = t1 * (1.0f / D);
        float var = t2 * (1.0f / D) - mu * mu;
        mu_s = mu;
        rstd_s = rsqrtf(fmaxf(var, 0.f) + 1e-5f);
    }
    __syncthreads();
    const float mu = mu_s, rstd = rstd_s;

    float4 g4 = ((const float4*)g)[tid];
    float4 b4 = ((const float4*)be)[tid];
    float4 o4;
    o4.x = (v.x - mu) * rstd * g4.x + b4.x;
    o4.y = (v.y - mu) * rstd * g4.y + b4.y;
    o4.z = (v.z - mu) * rstd * g4.z + b4.z;
    o4.w = (v.w - mu) * rstd * g4.w + b4.w;
    ((float4*)out)[base + tid] = o4;
    if (WH) {
        __half2* xh2 = (__half2*)g_xh + base * 2 + tid * 2;
        xh2[0] = __floats2half2_rn(o4.x, o4.y);
        xh2[1] = __floats2half2_rn(o4.z, o4.w);
    }
}

// ============================================================
extern "C" void kernel_launch(void* const* d_in, const int* in_sizes, int n_in,
                              void* d_out, int out_size)
{
    const float* tgt  = (const float*)d_in[0];
    const float* mem  = (const float*)d_in[1];
    const float* pos  = (const float*)d_in[2];
    const float* qpos = (const float*)d_in[3];
    const int*   aidx = (const int*)d_in[4];
    const float* Wt2  = (const float*)d_in[5];
    const float* bt2  = (const float*)d_in[6];
    const float* W1   = (const float*)d_in[7];
    const float* b1   = (const float*)d_in[8];
    const float* W2   = (const float*)d_in[9];
    const float* b2   = (const float*)d_in[10];
    const float* g2   = (const float*)d_in[11];
    const float* be2  = (const float*)d_in[12];
    const float* g3   = (const float*)d_in[13];
    const float* be3  = (const float*)d_in[14];
    float* out = (float*)d_out;

    __half *rctx_p, *xh_p, *h_p, *wh_p;
    float *x_p, *part_p;
    cudaGetSymbolAddress((void**)&rctx_p, g_rctx_h);
    cudaGetSymbolAddress((void**)&xh_p,   g_xh);
    cudaGetSymbolAddress((void**)&h_p,    g_h);
    cudaGetSymbolAddress((void**)&wh_p,   g_wh);
    cudaGetSymbolAddress((void**)&x_p,    g_x);
    cudaGetSymbolAddress((void**)&part_p, g_part);

    const __half* whT2 = wh_p;
    const __half* wh1  = wh_p + D * D;
    const __half* wh2  = wh_p + D * D + (size_t)DFF * D;

    // 0) weights fp32 -> fp16
    cvt_kernel<<<dim3(128, 3), 256>>>(Wt2, W1, W2);

    // 1a) scores (frame-parallel, exactly-once read of mem+pos)
    score_kernel<<<T / 64, 256>>>(tgt, mem, pos, qpos, aidx);
    // 1b) softmax + ctx -> relu -> fp16
    ctx_kernel<<<S, 128>>>(mem);

    // 2) tgt2 partials = rctx @ Wt2^T   [512,512,K=512], splitK=4
    gemm_h<4, 0><<<dim3(D / 64, S / 64, 4), 128>>>(rctx_p, whT2, nullptr, part_p, S, D, D);

    // 3) x = LN(tgt + sum parts + bt2); also fp16 x
    ln_kernel<4, true><<<S, 128>>>(part_p, bt2, tgt, g2, be2, x_p);

    // 4) h = relu(x @ W1^T + b1) fp16   [512,2048,K=512]
    gemm_h<1, 1><<<dim3(DFF / 64, S / 64, 1), 128>>>(xh_p, wh1, b1, h_p, S, DFF, D);

    // 5) ffn partials = h @ W2^T   [512,512,K=2048], splitK=4
    gemm_h<4, 0><<<dim3(D / 64, S / 64, 4), 128>>>(h_p, wh2, nullptr, part_p, S, D, DFF);

    // 6) out = LN(x + sum parts + b2)
    ln_kernel<4, false><<<S, 128>>>(part_p, b2, x_p, g3, be3, out);
}

// round 10
// speedup vs baseline: 1.1622x; 1.1622x over previous
#include <cuda_runtime.h>
#include <cuda_fp16.h>
#include <cstdint>
#include <mma.h>
#include <math.h>

using namespace nvcuda;

#define S   512
#define T   16384
#define D   512
#define DFF 2048
#define SEG (T / S)          // 32 frames per segment
#define G   4                // queries per attention block

// -------- scratch (allocation-free: __device__ globals) --------
__device__ __half g_rctx_h[S * D];            // relu(ctx) fp16
__device__ __half g_xh[S * D];                // x fp16 (GEMM A)
__device__ __half g_h[S * DFF];               // relu FFN hidden fp16
__device__ __half g_wh[D * D + DFF * D + D * DFF];  // fp16 weights
__device__ float  g_x[S * D];                 // x fp32 (residual)
__device__ float  g_part[4 * S * D];          // split-K partials

// ============================================================
// cp.async helpers
// ============================================================
__device__ __forceinline__ void cp_async16(void* sm, const void* gm) {
    unsigned int a = (unsigned int)__cvta_generic_to_shared(sm);
    asm volatile("cp.async.cg.shared.global [%0], [%1], 16;" :: "r"(a), "l"(gm) : "memory");
}
__device__ __forceinline__ void cp_commit() {
    asm volatile("cp.async.commit_group;" ::: "memory");
}
__device__ __forceinline__ void cp_wait1() {
    asm volatile("cp.async.wait_group 1;" ::: "memory");
}

// ============================================================
// Weight conversion fp32 -> fp16 (once per launch, 3 matrices)
// ============================================================
__global__ __launch_bounds__(256) void cvt_kernel(
    const float* __restrict__ w0, const float* __restrict__ w1,
    const float* __restrict__ w2)
{
    const int mat = blockIdx.y;
    const float2* src;
    __half2* dst;
    int n2;
    if (mat == 0) { src = (const float2*)w0; dst = (__half2*)g_wh;                 n2 = D * D / 2; }
    else if (mat == 1) { src = (const float2*)w1; dst = (__half2*)(g_wh + D * D);  n2 = DFF * D / 2; }
    else { src = (const float2*)w2; dst = (__half2*)(g_wh + D * D + DFF * D);      n2 = D * DFF / 2; }
    for (int i = blockIdx.x * 256 + threadIdx.x; i < n2; i += gridDim.x * 256)
        dst[i] = __float22half2_rn(src[i]);
}

// ============================================================
// Kernel 1: banded attention -> relu(ctx) fp16. G=4 queries/block.
// 512 threads = 16 warps. Score loop: 2 frames in flight per warp.
// (R8 version — proven fastest.)
// ============================================================
__global__ __launch_bounds__(512) void attn_kernel(
    const float* __restrict__ tgt, const float* __restrict__ mem,
    const float* __restrict__ pos, const float* __restrict__ qpos,
    const int*   __restrict__ aidx)
{
    const int blk  = blockIdx.x;
    const int tid  = threadIdx.x;
    const int warp = tid >> 5, lane = tid & 31;
    const int q0   = blk * G;

    const int t0 = max(0, q0 - 1) * SEG;
    const int t1 = min(S, q0 + G + 1) * SEG;
    const int nf = t1 - t0;                      // 160 or 192

    __shared__ float4 qs[G][D / 4];
    __shared__ float  sp[G][(G + 2) * SEG];
    __shared__ float  invd[G];

    for (int i = tid; i < G * (D / 4); i += 512) {
        int qi = i / (D / 4), d4 = i % (D / 4);
        float4 tv = ((const float4*)tgt)[(size_t)(q0 + qi) * (D / 4) + d4];
        float4 pv = ((const float4*)qpos)[(size_t)(q0 + qi) * (D / 4) + d4];
        qs[qi][d4] = make_float4(tv.x + pv.x, tv.y + pv.y, tv.z + pv.z, tv.w + pv.w);
    }
    __syncthreads();

    const float scale = 0.04419417382415922f;  // 1/sqrt(512)

    for (int base = warp; base < nf; base += 32) {
        const int fA = base;
        const int fB = base + 16;
        const bool hasB = fB < nf;
        const int tA = t0 + fA;
        const int tB = t0 + (hasB ? fB : fA);
        const float4* mA = (const float4*)mem + (size_t)tA * (D / 4);
        const float4* pA = (const float4*)pos + (size_t)tA * (D / 4);
        const float4* mB = (const float4*)mem + (size_t)tB * (D / 4);
        const float4* pB = (const float4*)pos + (size_t)tB * (D / 4);

        float aA0 = 0.f, aA1 = 0.f, aA2 = 0.f, aA3 = 0.f;
        float aB0 = 0.f, aB1 = 0.f, aB2 = 0.f, aB3 = 0.f;
        #pragma unroll
        for (int i = 0; i < 4; i++) {
            const int d4 = lane + 32 * i;
            float4 ma = mA[d4], pa = pA[d4];
            float4 mb = mB[d4], pb = pB[d4];
            float4 kA = make_float4(ma.x + pa.x, ma.y + pa.y, ma.z + pa.z, ma.w + pa.w);
            float4 kB = make_float4(mb.x + pb.x, mb.y + pb.y, mb.z + pb.z, mb.w + pb.w);
            float4 qa = qs[0][d4], qb = qs[1][d4], qc = qs[2][d4], qd = qs[3][d4];
            aA0 = fmaf(kA.x, qa.x, fmaf(kA.y, qa.y, fmaf(kA.z, qa.z, fmaf(kA.w, qa.w, aA0))));
            aA1 = fmaf(kA.x, qb.x, fmaf(kA.y, qb.y, fmaf(kA.z, qb.z, fmaf(kA.w, qb.w, aA1))));
            aA2 = fmaf(kA.x, qc.x, fmaf(kA.y, qc.y, fmaf(kA.z, qc.z, fmaf(kA.w, qc.w, aA2))));
            aA3 = fmaf(kA.x, qd.x, fmaf(kA.y, qd.y, fmaf(kA.z, qd.z, fmaf(kA.w, qd.w, aA3))));
            aB0 = fmaf(kB.x, qa.x, fmaf(kB.y, qa.y, fmaf(kB.z, qa.z, fmaf(kB.w, qa.w, aB0))));
            aB1 = fmaf(kB.x, qb.x, fmaf(kB.y, qb.y, fmaf(kB.z, qb.z, fmaf(kB.w, qb.w, aB1))));
            aB2 = fmaf(kB.x, qc.x, fmaf(kB.y, qc.y, fmaf(kB.z, qc.z, fmaf(kB.w, qc.w, aB2))));
            aB3 = fmaf(kB.x, qd.x, fmaf(kB.y, qd.y, fmaf(kB.z, qd.z, fmaf(kB.w, qd.w, aB3))));
        }
        #pragma unroll
        for (int o = 16; o > 0; o >>= 1) {
            aA0 += __shfl_xor_sync(0xffffffffu, aA0, o);
            aA1 += __shfl_xor_sync(0xffffffffu, aA1, o);
            aA2 += __shfl_xor_sync(0xffffffffu, aA2, o);
            aA3 += __shfl_xor_sync(0xffffffffu, aA3, o);
            aB0 += __shfl_xor_sync(0xffffffffu, aB0, o);
            aB1 += __shfl_xor_sync(0xffffffffu, aB1, o);
            aB2 += __shfl_xor_sync(0xffffffffu, aB2, o);
            aB3 += __shfl_xor_sync(0xffffffffu, aB3, o);
        }
        if (lane == 0) {
            {
                const int a = aidx[tA];
                int d0 = a - q0;     if (d0 < 0) d0 = -d0;
                int d1 = a - q0 - 1; if (d1 < 0) d1 = -d1;
                int d2 = a - q0 - 2; if (d2 < 0) d2 = -d2;
                int d3 = a - q0 - 3; if (d3 < 0) d3 = -d3;
                sp[0][fA] = (d0 <= 1) ? aA0 * scale : -INFINITY;
                sp[1][fA] = (d1 <= 1) ? aA1 * scale : -INFINITY;
                sp[2][fA] = (d2 <= 1) ? aA2 * scale : -INFINITY;
                sp[3][fA] = (d3 <= 1) ? aA3 * scale : -INFINITY;
            }
            if (hasB) {
                const int a = aidx[tB];
                int d0 = a - q0;     if (d0 < 0) d0 = -d0;
                int d1 = a - q0 - 1; if (d1 < 0) d1 = -d1;
                int d2 = a - q0 - 2; if (d2 < 0) d2 = -d2;
                int d3 = a - q0 - 3; if (d3 < 0) d3 = -d3;
                sp[0][fB] = (d0 <= 1) ? aB0 * scale : -INFINITY;
                sp[1][fB] = (d1 <= 1) ? aB1 * scale : -INFINITY;
                sp[2][fB] = (d2 <= 1) ? aB2 * scale : -INFINITY;
                sp[3][fB] = (d3 <= 1) ? aB3 * scale : -INFINITY;
            }
        }
    }
    __syncthreads();

    if (warp < G) {
        const int qi = warp;
        float m = -INFINITY;
        for (int f = lane; f < nf; f += 32) m = fmaxf(m, sp[qi][f]);
        #pragma unroll
        for (int o = 16; o > 0; o >>= 1)
            m = fmaxf(m, __shfl_xor_sync(0xffffffffu, m, o));
        float ssum = 0.f;
        for (int f = lane; f < nf; f += 32) {
            float e = __expf(sp[qi][f] - m);
            sp[qi][f] = e;
            ssum += e;
        }
        #pragma unroll
        for (int o = 16; o > 0; o >>= 1)
            ssum += __shfl_xor_sync(0xffffffffu, ssum, o);
        if (lane == 0) invd[qi] = 1.f / ssum;
    }
    __syncthreads();

    // ctx -> relu -> fp16
    {
        const int qi = tid >> 7;
        const int dc = tid & 127;
        const int s  = q0 + qi;
        const int fb = max(0, s - 1) * SEG - t0;
        const int fe = min(S, s + 2) * SEG - t0;
        const float4* m4 = (const float4*)mem;
        float4 acc = make_float4(0.f, 0.f, 0.f, 0.f);
        #pragma unroll 4
        for (int f = fb; f < fe; f++) {
            const float p = sp[qi][f];
            float4 mv = m4[(size_t)(t0 + f) * (D / 4) + dc];
            acc.x = fmaf(p, mv.x, acc.x);
            acc.y = fmaf(p, mv.y, acc.y);
            acc.z = fmaf(p, mv.z, acc.z);
            acc.w = fmaf(p, mv.w, acc.w);
        }
        const float iv = invd[qi];
        acc.x = fmaxf(acc.x * iv, 0.f);
        acc.y = fmaxf(acc.y * iv, 0.f);
        acc.z = fmaxf(acc.z * iv, 0.f);
        acc.w = fmaxf(acc.w * iv, 0.f);
        __half2* outp = (__half2*)g_rctx_h + (size_t)s * (D / 2) + dc * 2;
        outp[0] = __floats2half2_rn(acc.x, acc.y);
        outp[1] = __floats2half2_rn(acc.z, acc.w);
    }
}

// ============================================================
// FP16 tensor-core GEMM, double-buffered cp.async.
// BM=BN=64, BK=64, 128 threads (4 warps, 32x32 warp tiles).
// MODE 0: fp32 raw partials to ((float*)C) + z*M*N
// MODE 1: relu(acc + bias) -> fp16 to (half*)C
// ============================================================
template <int KSPLIT, int MODE>
__global__ __launch_bounds__(128) void gemm_h(
    const __half* __restrict__ A, const __half* __restrict__ W,
    const float* __restrict__ bias, void* __restrict__ C,
    int M, int N, int K)
{
    constexpr int BM = 64, BN = 64, BK = 64;
    constexpr int LDA = BK + 8;
    constexpr int LDC = BN + 4;

    __shared__ union SmemU {
        struct { __half A[2][BM][LDA]; __half B[2][BN][LDA]; } s;
        float Cs[BM][LDC];
    } sm;

    const int tid  = threadIdx.x;
    const int warp = tid >> 5;
    const int wm = warp >> 1, wn = warp & 1;
    const int col0 = blockIdx.x * BN;
    const int row0 = blockIdx.y * BM;
    const int Kloc = K / KSPLIT;
    const int kbase = blockIdx.z * Kloc;

    wmma::fragment<wmma::accumulator, 16, 16, 16, float> acc[2][2];
    #pragma unroll
    for (int i = 0; i < 2; i++)
        #pragma unroll
        for (int j = 0; j < 2; j++)
            wmma::fill_fragment(acc[i][j], 0.f);

    const int NIT = Kloc / BK;

    auto load_tile = [&](int it, int st) {
        const int k0 = kbase + it * BK;
        #pragma unroll
        for (int i = tid; i < BM * (BK / 8); i += 128) {
            int r = i >> 3, c = (i & 7) * 8;
            cp_async16(&sm.s.A[st][r][c], &A[(size_t)(row0 + r) * K + k0 + c]);
        }
        #pragma unroll
        for (int i = tid; i < BN * (BK / 8); i += 128) {
            int r = i >> 3, c = (i & 7) * 8;
            cp_async16(&sm.s.B[st][r][c], &W[(size_t)(col0 + r) * K + k0 + c]);
        }
    };

    load_tile(0, 0);
    cp_commit();

    for (int it = 0; it < NIT; it++) {
        if (it + 1 < NIT) load_tile(it + 1, (it + 1) & 1);
        cp_commit();
        cp_wait1();
        __syncthreads();

        const int st = it & 1;
        #pragma unroll
        for (int kk = 0; kk < BK; kk += 16) {
            wmma::fragment<wmma::matrix_a, 16, 16, 16, __half, wmma::row_major> fa[2];
            wmma::fragment<wmma::matrix_b, 16, 16, 16, __half, wmma::col_major> fb[2];
            #pragma unroll
            for (int i = 0; i < 2; i++)
                wmma::load_matrix_sync(fa[i], &sm.s.A[st][wm * 32 + i * 16][kk], LDA);
            #pragma unroll
            for (int j = 0; j < 2; j++)
                wmma::load_matrix_sync(fb[j], &sm.s.B[st][wn * 32 + j * 16][kk], LDA);
            #pragma unroll
            for (int i = 0; i < 2; i++)
                #pragma unroll
                for (int j = 0; j < 2; j++)
                    wmma::mma_sync(acc[i][j], fa[i], fb[j], acc[i][j]);
        }
        __syncthreads();
    }

    #pragma unroll
    for (int i = 0; i < 2; i++)
        #pragma unroll
        for (int j = 0; j < 2; j++)
            wmma::store_matrix_sync(&sm.Cs[wm * 32 + i * 16][wn * 32 + j * 16],
                                    acc[i][j], LDC, wmma::mem_row_major);
    __syncthreads();

    if (MODE == 0) {
        float* Co = (float*)C + (size_t)blockIdx.z * M * N;
        #pragma unroll
        for (int i = tid; i < BM * (BN / 4); i += 128) {
            int r = i / (BN / 4), c = (i % (BN / 4)) * 4;
            float4 v = *(float4*)&sm.Cs[r][c];
            *(float4*)&Co[(size_t)(row0 + r) * N + col0 + c] = v;
        }
    } else {
        __half* Co = (__half*)C;
        #pragma unroll
        for (int i = tid; i < BM * (BN / 4); i += 128) {
            int r = i / (BN / 4), c = (i % (BN / 4)) * 4;
            float4 v = *(float4*)&sm.Cs[r][c];
            float4 b4 = *(const float4*)&bias[col0 + c];
            v.x = fmaxf(v.x + b4.x, 0.f);
            v.y = fmaxf(v.y + b4.y, 0.f);
            v.z = fmaxf(v.z + b4.z, 0.f);
            v.w = fmaxf(v.w + b4.w, 0.f);
            __half2* o2 = (__half2*)&Co[(size_t)(row0 + r) * N + col0 + c];
            o2[0] = __floats2half2_rn(v.x, v.y);
            o2[1] = __floats2half2_rn(v.z, v.w);
        }
    }
}

// ============================================================
// LayerNorm, vectorized, single reduction round (sum, sumsq).
// v = sum_k parts[k] + res + bias; out = LN(v)*g + be.
// WH: also write fp16 x to g_xh.
// ============================================================
template <int NP, bool WH>
__global__ __launch_bounds__(128) void ln_kernel(
    const float* __restrict__ parts,
    const float* __restrict__ bias, const float* __restrict__ res,
    const float* __restrict__ g, const float* __restrict__ be,
    float* __restrict__ out)
{
    const int row = blockIdx.x;
    const int tid = threadIdx.x;           // 0..127, one float4 each
    const size_t base = (size_t)row * (D / 4);

    float4 v = ((const float4*)res)[base + tid];
    {
        float4 b4 = ((const float4*)bias)[tid];
        v.x += b4.x; v.y += b4.y; v.z += b4.z; v.w += b4.w;
    }
    #pragma unroll
    for (int k = 0; k < NP; k++) {
        float4 pv = ((const float4*)parts)[(size_t)k * S * (D / 4) + base + tid];
        v.x += pv.x; v.y += pv.y; v.z += pv.z; v.w += pv.w;
    }

    float s1 = v.x + v.y + v.z + v.w;
    float s2 = v.x * v.x + v.y * v.y + v.z * v.z + v.w * v.w;

    __shared__ float r1[4], r2[4];
    __shared__ float mu_s, rstd_s;
    #pragma unroll
    for (int o = 16; o > 0; o >>= 1) {
        s1 += __shfl_xor_sync(0xffffffffu, s1, o);
        s2 += __shfl_xor_sync(0xffffffffu, s2, o);
    }
    if ((tid & 31) == 0) { r1[tid >> 5] = s1; r2[tid >> 5] = s2; }
    __syncthreads();
    if (tid == 0) {
        float t1 = r1[0] + r1[1] + r1[2] + r1[3];
        float t2 = r2[0] + r2[1] + r2[2] + r2[3];
        const float mu = t1 * (1.0f / D);
        float var = t2 * (1.0f / D) - mu * mu;
        mu_s = mu;
        rstd_s = rsqrtf(fmaxf(var, 0.f) + 1e-5f);
    }
    __syncthreads();
    const float mu = mu_s, rstd = rstd_s;

    float4 g4 = ((const float4*)g)[tid];
    float4 b4 = ((const float4*)be)[tid];
    float4 o4;
    o4.x = (v.x - mu) * rstd * g4.x + b4.x;
    o4.y = (v.y - mu) * rstd * g4.y + b4.y;
    o4.z = (v.z - mu) * rstd * g4.z + b4.z;
    o4.w = (v.w - mu) * rstd * g4.w + b4.w;
    ((float4*)out)[base + tid] = o4;
    if (WH) {
        __half2* xh2 = (__half2*)g_xh + base * 2 + tid * 2;
        xh2[0] = __floats2half2_rn(o4.x, o4.y);
        xh2[1] = __floats2half2_rn(o4.z, o4.w);
    }
}

// ============================================================
extern "C" void kernel_launch(void* const* d_in, const int* in_sizes, int n_in,
                              void* d_out, int out_size)
{
    const float* tgt  = (const float*)d_in[0];
    const float* mem  = (const float*)d_in[1];
    const float* pos  = (const float*)d_in[2];
    const float* qpos = (const float*)d_in[3];
    const int*   aidx = (const int*)d_in[4];
    const float* Wt2  = (const float*)d_in[5];
    const float* bt2  = (const float*)d_in[6];
    const float* W1   = (const float*)d_in[7];
    const float* b1   = (const float*)d_in[8];
    const float* W2   = (const float*)d_in[9];
    const float* b2   = (const float*)d_in[10];
    const float* g2   = (const float*)d_in[11];
    const float* be2  = (const float*)d_in[12];
    const float* g3   = (const float*)d_in[13];
    const float* be3  = (const float*)d_in[14];
    float* out = (float*)d_out;

    __half *rctx_p, *xh_p, *h_p, *wh_p;
    float *x_p, *part_p;
    cudaGetSymbolAddress((void**)&rctx_p, g_rctx_h);
    cudaGetSymbolAddress((void**)&xh_p,   g_xh);
    cudaGetSymbolAddress((void**)&h_p,    g_h);
    cudaGetSymbolAddress((void**)&wh_p,   g_wh);
    cudaGetSymbolAddress((void**)&x_p,    g_x);
    cudaGetSymbolAddress((void**)&part_p, g_part);

    const __half* whT2 = wh_p;
    const __half* wh1  = wh_p + D * D;
    const __half* wh2  = wh_p + D * D + (size_t)DFF * D;

    // 0) weights fp32 -> fp16
    cvt_kernel<<<dim3(128, 3), 256>>>(Wt2, W1, W2);

    // 1) attention -> relu(ctx) fp16
    attn_kernel<<<S / G, 512>>>(tgt, mem, pos, qpos, aidx);

    // 2) tgt2 partials = rctx @ Wt2^T   [512,512,K=512], splitK=4
    gemm_h<4, 0><<<dim3(D / 64, S / 64, 4), 128>>>(rctx_p, whT2, nullptr, part_p, S, D, D);

    // 3) x = LN(tgt + sum parts + bt2); also fp16 x
    ln_kernel<4, true><<<S, 128>>>(part_p, bt2, tgt, g2, be2, x_p);

    // 4) h = relu(x @ W1^T + b1) fp16   [512,2048,K=512]
    gemm_h<1, 1><<<dim3(DFF / 64, S / 64, 1), 128>>>(xh_p, wh1, b1, h_p, S, DFF, D);

    // 5) ffn partials = h @ W2^T   [512,512,K=2048], splitK=4
    gemm_h<4, 0><<<dim3(D / 64, S / 64, 4), 128>>>(h_p, wh2, nullptr, part_p, S, D, DFF);

    // 6) out = LN(x + sum parts + b2)
    ln_kernel<4, false><<<S, 128>>>(part_p, b2, x_p, g3, be3, out);
}

// round 11
// speedup vs baseline: 1.1930x; 1.0265x over previous
#include <cuda_runtime.h>
#include <cuda_fp16.h>
#include <cstdint>
#include <mma.h>
#include <math.h>

using namespace nvcuda;

#define S   512
#define T   16384
#define D   512
#define DFF 2048
#define SEG (T / S)          // 32 frames per segment
#define G   4                // queries per attention block

// -------- scratch (allocation-free: __device__ globals) --------
__device__ __half g_rctx_h[S * D];            // relu(ctx) fp16
__device__ __half g_xh[S * D];                // x fp16 (GEMM A)
__device__ __half g_h[S * DFF];               // relu FFN hidden fp16
__device__ __half g_wh[D * D + DFF * D + D * DFF];  // fp16 weights
__device__ float  g_x[S * D];                 // x fp32 (residual)
__device__ float  g_part[2 * S * D];          // split-K partials

// ============================================================
// cp.async helpers
// ============================================================
__device__ __forceinline__ void cp_async16(void* sm, const void* gm) {
    unsigned int a = (unsigned int)__cvta_generic_to_shared(sm);
    asm volatile("cp.async.cg.shared.global [%0], [%1], 16;" :: "r"(a), "l"(gm) : "memory");
}
__device__ __forceinline__ void cp_commit() {
    asm volatile("cp.async.commit_group;" ::: "memory");
}
__device__ __forceinline__ void cp_wait2() {
    asm volatile("cp.async.wait_group 2;" ::: "memory");
}

// ============================================================
// Weight conversion fp32 -> fp16 (once per launch, 3 matrices)
// ============================================================
__global__ __launch_bounds__(256) void cvt_kernel(
    const float* __restrict__ w0, const float* __restrict__ w1,
    const float* __restrict__ w2)
{
    const int mat = blockIdx.y;
    const float2* src;
    __half2* dst;
    int n2;
    if (mat == 0) { src = (const float2*)w0; dst = (__half2*)g_wh;                 n2 = D * D / 2; }
    else if (mat == 1) { src = (const float2*)w1; dst = (__half2*)(g_wh + D * D);  n2 = DFF * D / 2; }
    else { src = (const float2*)w2; dst = (__half2*)(g_wh + D * D + DFF * D);      n2 = D * DFF / 2; }
    for (int i = blockIdx.x * 256 + threadIdx.x; i < n2; i += gridDim.x * 256)
        dst[i] = __float22half2_rn(src[i]);
}

// ============================================================
// Kernel 1: banded attention -> relu(ctx) fp16. G=4 queries/block.
// 512 threads = 16 warps. (R8 version — proven fastest.)
// ============================================================
__global__ __launch_bounds__(512) void attn_kernel(
    const float* __restrict__ tgt, const float* __restrict__ mem,
    const float* __restrict__ pos, const float* __restrict__ qpos,
    const int*   __restrict__ aidx)
{
    const int blk  = blockIdx.x;
    const int tid  = threadIdx.x;
    const int warp = tid >> 5, lane = tid & 31;
    const int q0   = blk * G;

    const int t0 = max(0, q0 - 1) * SEG;
    const int t1 = min(S, q0 + G + 1) * SEG;
    const int nf = t1 - t0;                      // 160 or 192

    __shared__ float4 qs[G][D / 4];
    __shared__ float  sp[G][(G + 2) * SEG];
    __shared__ float  invd[G];

    for (int i = tid; i < G * (D / 4); i += 512) {
        int qi = i / (D / 4), d4 = i % (D / 4);
        float4 tv = ((const float4*)tgt)[(size_t)(q0 + qi) * (D / 4) + d4];
        float4 pv = ((const float4*)qpos)[(size_t)(q0 + qi) * (D / 4) + d4];
        qs[qi][d4] = make_float4(tv.x + pv.x, tv.y + pv.y, tv.z + pv.z, tv.w + pv.w);
    }
    __syncthreads();

    const float scale = 0.04419417382415922f;  // 1/sqrt(512)

    for (int base = warp; base < nf; base += 32) {
        const int fA = base;
        const int fB = base + 16;
        const bool hasB = fB < nf;
        const int tA = t0 + fA;
        const int tB = t0 + (hasB ? fB : fA);
        const float4* mA = (const float4*)mem + (size_t)tA * (D / 4);
        const float4* pA = (const float4*)pos + (size_t)tA * (D / 4);
        const float4* mB = (const float4*)mem + (size_t)tB * (D / 4);
        const float4* pB = (const float4*)pos + (size_t)tB * (D / 4);

        float aA0 = 0.f, aA1 = 0.f, aA2 = 0.f, aA3 = 0.f;
        float aB0 = 0.f, aB1 = 0.f, aB2 = 0.f, aB3 = 0.f;
        #pragma unroll
        for (int i = 0; i < 4; i++) {
            const int d4 = lane + 32 * i;
            float4 ma = mA[d4], pa = pA[d4];
            float4 mb = mB[d4], pb = pB[d4];
            float4 kA = make_float4(ma.x + pa.x, ma.y + pa.y, ma.z + pa.z, ma.w + pa.w);
            float4 kB = make_float4(mb.x + pb.x, mb.y + pb.y, mb.z + pb.z, mb.w + pb.w);
            float4 qa = qs[0][d4], qb = qs[1][d4], qc = qs[2][d4], qd = qs[3][d4];
            aA0 = fmaf(kA.x, qa.x, fmaf(kA.y, qa.y, fmaf(kA.z, qa.z, fmaf(kA.w, qa.w, aA0))));
            aA1 = fmaf(kA.x, qb.x, fmaf(kA.y, qb.y, fmaf(kA.z, qb.z, fmaf(kA.w, qb.w, aA1))));
            aA2 = fmaf(kA.x, qc.x, fmaf(kA.y, qc.y, fmaf(kA.z, qc.z, fmaf(kA.w, qc.w, aA2))));
            aA3 = fmaf(kA.x, qd.x, fmaf(kA.y, qd.y, fmaf(kA.z, qd.z, fmaf(kA.w, qd.w, aA3))));
            aB0 = fmaf(kB.x, qa.x, fmaf(kB.y, qa.y, fmaf(kB.z, qa.z, fmaf(kB.w, qa.w, aB0))));
            aB1 = fmaf(kB.x, qb.x, fmaf(kB.y, qb.y, fmaf(kB.z, qb.z, fmaf(kB.w, qb.w, aB1))));
            aB2 = fmaf(kB.x, qc.x, fmaf(kB.y, qc.y, fmaf(kB.z, qc.z, fmaf(kB.w, qc.w, aB2))));
            aB3 = fmaf(kB.x, qd.x, fmaf(kB.y, qd.y, fmaf(kB.z, qd.z, fmaf(kB.w, qd.w, aB3))));
        }
        #pragma unroll
        for (int o = 16; o > 0; o >>= 1) {
            aA0 += __shfl_xor_sync(0xffffffffu, aA0, o);
            aA1 += __shfl_xor_sync(0xffffffffu, aA1, o);
            aA2 += __shfl_xor_sync(0xffffffffu, aA2, o);
            aA3 += __shfl_xor_sync(0xffffffffu, aA3, o);
            aB0 += __shfl_xor_sync(0xffffffffu, aB0, o);
            aB1 += __shfl_xor_sync(0xffffffffu, aB1, o);
            aB2 += __shfl_xor_sync(0xffffffffu, aB2, o);
            aB3 += __shfl_xor_sync(0xffffffffu, aB3, o);
        }
        if (lane == 0) {
            {
                const int a = aidx[tA];
                int d0 = a - q0;     if (d0 < 0) d0 = -d0;
                int d1 = a - q0 - 1; if (d1 < 0) d1 = -d1;
                int d2 = a - q0 - 2; if (d2 < 0) d2 = -d2;
                int d3 = a - q0 - 3; if (d3 < 0) d3 = -d3;
                sp[0][fA] = (d0 <= 1) ? aA0 * scale : -INFINITY;
                sp[1][fA] = (d1 <= 1) ? aA1 * scale : -INFINITY;
                sp[2][fA] = (d2 <= 1) ? aA2 * scale : -INFINITY;
                sp[3][fA] = (d3 <= 1) ? aA3 * scale : -INFINITY;
            }
            if (hasB) {
                const int a = aidx[tB];
                int d0 = a - q0;     if (d0 < 0) d0 = -d0;
                int d1 = a - q0 - 1; if (d1 < 0) d1 = -d1;
                int d2 = a - q0 - 2; if (d2 < 0) d2 = -d2;
                int d3 = a - q0 - 3; if (d3 < 0) d3 = -d3;
                sp[0][fB] = (d0 <= 1) ? aB0 * scale : -INFINITY;
                sp[1][fB] = (d1 <= 1) ? aB1 * scale : -INFINITY;
                sp[2][fB] = (d2 <= 1) ? aB2 * scale : -INFINITY;
                sp[3][fB] = (d3 <= 1) ? aB3 * scale : -INFINITY;
            }
        }
    }
    __syncthreads();

    if (warp < G) {
        const int qi = warp;
        float m = -INFINITY;
        for (int f = lane; f < nf; f += 32) m = fmaxf(m, sp[qi][f]);
        #pragma unroll
        for (int o = 16; o > 0; o >>= 1)
            m = fmaxf(m, __shfl_xor_sync(0xffffffffu, m, o));
        float ssum = 0.f;
        for (int f = lane; f < nf; f += 32) {
            float e = __expf(sp[qi][f] - m);
            sp[qi][f] = e;
            ssum += e;
        }
        #pragma unroll
        for (int o = 16; o > 0; o >>= 1)
            ssum += __shfl_xor_sync(0xffffffffu, ssum, o);
        if (lane == 0) invd[qi] = 1.f / ssum;
    }
    __syncthreads();

    // ctx -> relu -> fp16
    {
        const int qi = tid >> 7;
        const int dc = tid & 127;
        const int s  = q0 + qi;
        const int fb = max(0, s - 1) * SEG - t0;
        const int fe = min(S, s + 2) * SEG - t0;
        const float4* m4 = (const float4*)mem;
        float4 acc = make_float4(0.f, 0.f, 0.f, 0.f);
        #pragma unroll 4
        for (int f = fb; f < fe; f++) {
            const float p = sp[qi][f];
            float4 mv = m4[(size_t)(t0 + f) * (D / 4) + dc];
            acc.x = fmaf(p, mv.x, acc.x);
            acc.y = fmaf(p, mv.y, acc.y);
            acc.z = fmaf(p, mv.z, acc.z);
            acc.w = fmaf(p, mv.w, acc.w);
        }
        const float iv = invd[qi];
        acc.x = fmaxf(acc.x * iv, 0.f);
        acc.y = fmaxf(acc.y * iv, 0.f);
        acc.z = fmaxf(acc.z * iv, 0.f);
        acc.w = fmaxf(acc.w * iv, 0.f);
        __half2* outp = (__half2*)g_rctx_h + (size_t)s * (D / 2) + dc * 2;
        outp[0] = __floats2half2_rn(acc.x, acc.y);
        outp[1] = __floats2half2_rn(acc.z, acc.w);
    }
}

// ============================================================
// FP16 tensor-core GEMM, 3-stage cp.async pipeline, 256 threads.
// BM=64, BN template (64 or 128), BK=64. 8 warps.
//  BN=128: warp grid 2x4, warp tile 32x32 (TM=2,TN=2)
//  BN=64 : warp grid 4x2, warp tile 16x32 (TM=1,TN=2)
// MODE 0: fp32 raw partials to ((float*)C) + z*M*N
// MODE 1: relu(acc + bias) -> fp16 to (half*)C
// ============================================================
template <int BN, int KSPLIT, int MODE>
__global__ __launch_bounds__(256) void gemm_h(
    const __half* __restrict__ A, const __half* __restrict__ W,
    const float* __restrict__ bias, void* __restrict__ C,
    int M, int N, int K)
{
    constexpr int BM = 64, BK = 64;
    constexpr int NWN = BN / 32;          // warps along N (4 or 2)
    constexpr int NWM = 8 / NWN;          // warps along M (2 or 4)
    constexpr int WM  = BM / NWM;         // 32 or 16
    constexpr int TM  = WM / 16;          // 2 or 1
    constexpr int LDA = BK + 8;           // halfs
    constexpr int LDC = BN + 4;           // floats

    __shared__ union SmemU {
        struct { __half A[3][BM][LDA]; __half B[3][BN][LDA]; } s;
        float Cs[BM][LDC];
    } sm;

    const int tid  = threadIdx.x;
    const int warp = tid >> 5;
    const int wm = warp / NWN, wn = warp % NWN;
    const int col0 = blockIdx.x * BN;
    const int row0 = blockIdx.y * BM;
    const int Kloc = K / KSPLIT;
    const int kbase = blockIdx.z * Kloc;

    wmma::fragment<wmma::accumulator, 16, 16, 16, float> acc[TM][2];
    #pragma unroll
    for (int i = 0; i < TM; i++)
        #pragma unroll
        for (int j = 0; j < 2; j++)
            wmma::fill_fragment(acc[i][j], 0.f);

    const int NIT = Kloc / BK;

    auto load_tile = [&](int it, int st) {
        const int k0 = kbase + it * BK;
        #pragma unroll
        for (int i = tid; i < BM * (BK / 8); i += 256) {
            int r = i >> 3, c = (i & 7) * 8;
            cp_async16(&sm.s.A[st][r][c], &A[(size_t)(row0 + r) * K + k0 + c]);
        }
        #pragma unroll
        for (int i = tid; i < BN * (BK / 8); i += 256) {
            int r = i >> 3, c = (i & 7) * 8;
            cp_async16(&sm.s.B[st][r][c], &W[(size_t)(col0 + r) * K + k0 + c]);
        }
    };

    // prologue: 2 tiles in flight
    load_tile(0, 0);
    cp_commit();
    if (NIT > 1) load_tile(1, 1);
    cp_commit();

    for (int it = 0; it < NIT; it++) {
        if (it + 2 < NIT) load_tile(it + 2, (it + 2) % 3);
        cp_commit();
        cp_wait2();            // all groups older than 2 most-recent done => tile it ready
        __syncthreads();

        const int st = it % 3;
        #pragma unroll
        for (int kk = 0; kk < BK; kk += 16) {
            wmma::fragment<wmma::matrix_a, 16, 16, 16, __half, wmma::row_major> fa[TM];
            wmma::fragment<wmma::matrix_b, 16, 16, 16, __half, wmma::col_major> fb[2];
            #pragma unroll
            for (int i = 0; i < TM; i++)
                wmma::load_matrix_sync(fa[i], &sm.s.A[st][wm * WM + i * 16][kk], LDA);
            #pragma unroll
            for (int j = 0; j < 2; j++)
                wmma::load_matrix_sync(fb[j], &sm.s.B[st][wn * 32 + j * 16][kk], LDA);
            #pragma unroll
            for (int i = 0; i < TM; i++)
                #pragma unroll
                for (int j = 0; j < 2; j++)
                    wmma::mma_sync(acc[i][j], fa[i], fb[j], acc[i][j]);
        }
        __syncthreads();
    }

    // epilogue via smem (aliased)
    #pragma unroll
    for (int i = 0; i < TM; i++)
        #pragma unroll
        for (int j = 0; j < 2; j++)
            wmma::store_matrix_sync(&sm.Cs[wm * WM + i * 16][wn * 32 + j * 16],
                                    acc[i][j], LDC, wmma::mem_row_major);
    __syncthreads();

    if (MODE == 0) {
        float* Co = (float*)C + (size_t)blockIdx.z * M * N;
        #pragma unroll
        for (int i = tid; i < BM * (BN / 4); i += 256) {
            int r = i / (BN / 4), c = (i % (BN / 4)) * 4;
            float4 v = *(float4*)&sm.Cs[r][c];
            *(float4*)&Co[(size_t)(row0 + r) * N + col0 + c] = v;
        }
    } else {
        __half* Co = (__half*)C;
        #pragma unroll
        for (int i = tid; i < BM * (BN / 4); i += 256) {
            int r = i / (BN / 4), c = (i % (BN / 4)) * 4;
            float4 v = *(float4*)&sm.Cs[r][c];
            float4 b4 = *(const float4*)&bias[col0 + c];
            v.x = fmaxf(v.x + b4.x, 0.f);
            v.y = fmaxf(v.y + b4.y, 0.f);
            v.z = fmaxf(v.z + b4.z, 0.f);
            v.w = fmaxf(v.w + b4.w, 0.f);
            __half2* o2 = (__half2*)&Co[(size_t)(row0 + r) * N + col0 + c];
            o2[0] = __floats2half2_rn(v.x, v.y);
            o2[1] = __floats2half2_rn(v.z, v.w);
        }
    }
}

// ============================================================
// LayerNorm, vectorized, single reduction round (sum, sumsq).
// v = sum_k parts[k] + res + bias; out = LN(v)*g + be.
// ============================================================
template <int NP, bool WH>
__global__ __launch_bounds__(128) void ln_kernel(
    const float* __restrict__ parts,
    const float* __restrict__ bias, const float* __restrict__ res,
    const float* __restrict__ g, const float* __restrict__ be,
    float* __restrict__ out)
{
    const int row = blockIdx.x;
    const int tid = threadIdx.x;           // 0..127, one float4 each
    const size_t base = (size_t)row * (D / 4);

    float4 v = ((const float4*)res)[base + tid];
    {
        float4 b4 = ((const float4*)bias)[tid];
        v.x += b4.x; v.y += b4.y; v.z += b4.z; v.w += b4.w;
    }
    #pragma unroll
    for (int k = 0; k < NP; k++) {
        float4 pv = ((const float4*)parts)[(size_t)k * S * (D / 4) + base + tid];
        v.x += pv.x; v.y += pv.y; v.z += pv.z; v.w += pv.w;
    }

    float s1 = v.x + v.y + v.z + v.w;
    float s2 = v.x * v.x + v.y * v.y + v.z * v.z + v.w * v.w;

    __shared__ float r1[4], r2[4];
    __shared__ float mu_s, rstd_s;
    #pragma unroll
    for (int o = 16; o > 0; o >>= 1) {
        s1 += __shfl_xor_sync(0xffffffffu, s1, o);
        s2 += __shfl_xor_sync(0xffffffffu, s2, o);
    }
    if ((tid & 31) == 0) { r1[tid >> 5] = s1; r2[tid >> 5] = s2; }
    __syncthreads();
    if (tid == 0) {
        float t1 = r1[0] + r1[1] + r1[2] + r1[3];
        float t2 = r2[0] + r2[1] + r2[2] + r2[3];
        const float mu = t1 * (1.0f / D);
        float var = t2 * (1.0f / D) - mu * mu;
        mu_s = mu;
        rstd_s = rsqrtf(fmaxf(var, 0.f) + 1e-5f);
    }
    __syncthreads();
    const float mu = mu_s, rstd = rstd_s;

    float4 g4 = ((const float4*)g)[tid];
    float4 b4 = ((const float4*)be)[tid];
    float4 o4;
    o4.x = (v.x - mu) * rstd * g4.x + b4.x;
    o4.y = (v.y - mu) * rstd * g4.y + b4.y;
    o4.z = (v.z - mu) * rstd * g4.z + b4.z;
    o4.w = (v.w - mu) * rstd * g4.w + b4.w;
    ((float4*)out)[base + tid] = o4;
    if (WH) {
        __half2* xh2 = (__half2*)g_xh + base * 2 + tid * 2;
        xh2[0] = __floats2half2_rn(o4.x, o4.y);
        xh2[1] = __floats2half2_rn(o4.z, o4.w);
    }
}

// ============================================================
extern "C" void kernel_launch(void* const* d_in, const int* in_sizes, int n_in,
                              void* d_out, int out_size)
{
    const float* tgt  = (const float*)d_in[0];
    const float* mem  = (const float*)d_in[1];
    const float* pos  = (const float*)d_in[2];
    const float* qpos = (const float*)d_in[3];
    const int*   aidx = (const int*)d_in[4];
    const float* Wt2  = (const float*)d_in[5];
    const float* bt2  = (const float*)d_in[6];
    const float* W1   = (const float*)d_in[7];
    const float* b1   = (const float*)d_in[8];
    const float* W2   = (const float*)d_in[9];
    const float* b2   = (const float*)d_in[10];
    const float* g2   = (const float*)d_in[11];
    const float* be2  = (const float*)d_in[12];
    const float* g3   = (const float*)d_in[13];
    const float* be3  = (const float*)d_in[14];
    float* out = (float*)d_out;

    __half *rctx_p, *xh_p, *h_p, *wh_p;
    float *x_p, *part_p;
    cudaGetSymbolAddress((void**)&rctx_p, g_rctx_h);
    cudaGetSymbolAddress((void**)&xh_p,   g_xh);
    cudaGetSymbolAddress((void**)&h_p,    g_h);
    cudaGetSymbolAddress((void**)&wh_p,   g_wh);
    cudaGetSymbolAddress((void**)&x_p,    g_x);
    cudaGetSymbolAddress((void**)&part_p, g_part);

    const __half* whT2 = wh_p;
    const __half* wh1  = wh_p + D * D;
    const __half* wh2  = wh_p + D * D + (size_t)DFF * D;

    // 0) weights fp32 -> fp16
    cvt_kernel<<<dim3(128, 3), 256>>>(Wt2, W1, W2);

    // 1) attention -> relu(ctx) fp16
    attn_kernel<<<S / G, 512>>>(tgt, mem, pos, qpos, aidx);

    // 2) tgt2 partials = rctx @ Wt2^T   [512,512,K=512], splitK=2
    gemm_h<64, 2, 0><<<dim3(D / 64, S / 64, 2), 256>>>(rctx_p, whT2, nullptr, part_p, S, D, D);

    // 3) x = LN(tgt + p0 + p1 + bt2); also fp16 x
    ln_kernel<2, true><<<S, 128>>>(part_p, bt2, tgt, g2, be2, x_p);

    // 4) h = relu(x @ W1^T + b1) fp16   [512,2048,K=512]
    gemm_h<128, 1, 1><<<dim3(DFF / 128, S / 64, 1), 256>>>(xh_p, wh1, b1, h_p, S, DFF, D);

    // 5) ffn partials = h @ W2^T   [512,512,K=2048], splitK=2
    gemm_h<64, 2, 0><<<dim3(D / 64, S / 64, 2), 256>>>(h_p, wh2, nullptr, part_p, S, D, DFF);

    // 6) out = LN(x + p0 + p1 + b2)
    ln_kernel<2, false><<<S, 128>>>(part_p, b2, x_p, g3, be3, out);
}

// round 13
// speedup vs baseline: 1.2101x; 1.0144x over previous
#include <cuda_runtime.h>
#include <cuda_fp16.h>
#include <cstdint>
#include <mma.h>
#include <math.h>

using namespace nvcuda;

#define S   512
#define T   16384
#define D   512
#define DFF 2048
#define SEG (T / S)          // 32 frames per segment
#define G   4                // queries per attention block

// -------- scratch (allocation-free: __device__ globals) --------
__device__ __half g_rctx_h[S * D];            // relu(ctx) fp16
__device__ __half g_xh[S * D];                // x fp16 (GEMM A)
__device__ __half g_h[S * DFF];               // relu FFN hidden fp16
__device__ __half g_wh[D * D + DFF * D + D * DFF];  // fp16 weights
__device__ float  g_x[S * D];                 // x fp32 (residual)
__device__ float  g_part[2 * S * D];          // split-K partials

// ============================================================
// cp.async helpers
// ============================================================
__device__ __forceinline__ void cp_async16(void* sm, const void* gm) {
    unsigned int a = (unsigned int)__cvta_generic_to_shared(sm);
    asm volatile("cp.async.cg.shared.global [%0], [%1], 16;" :: "r"(a), "l"(gm) : "memory");
}
__device__ __forceinline__ void cp_commit() {
    asm volatile("cp.async.commit_group;" ::: "memory");
}
__device__ __forceinline__ void cp_wait2() {
    asm volatile("cp.async.wait_group 2;" ::: "memory");
}

__device__ __forceinline__ float dot4(float4 a, float4 b) {
    return fmaf(a.x, b.x, fmaf(a.y, b.y, fmaf(a.z, b.z, a.w * b.w)));
}

// ============================================================
// Weight conversion fp32 -> fp16 (once per launch, 3 matrices)
// ============================================================
__global__ __launch_bounds__(256) void cvt_kernel(
    const float* __restrict__ w0, const float* __restrict__ w1,
    const float* __restrict__ w2)
{
    const int mat = blockIdx.y;
    const float2* src;
    __half2* dst;
    int n2;
    if (mat == 0) { src = (const float2*)w0; dst = (__half2*)g_wh;                 n2 = D * D / 2; }
    else if (mat == 1) { src = (const float2*)w1; dst = (__half2*)(g_wh + D * D);  n2 = DFF * D / 2; }
    else { src = (const float2*)w2; dst = (__half2*)(g_wh + D * D + DFF * D);      n2 = D * DFF / 2; }
    for (int i = blockIdx.x * 256 + threadIdx.x; i < n2; i += gridDim.x * 256)
        dst[i] = __float22half2_rn(src[i]);
}

// ============================================================
// Kernel 1: banded attention -> relu(ctx) fp16. G=4 queries/block.
// 512 threads = 16 warps.
//   Score phase: only the <=3 valid (frame,query) dots per frame.
//   sp[qi][slot]: slot = (2-e)*32 + (t&31), qi = seg(t)-1-q0+e.
//   Ctx phase: single pass over the 6-seg union, 4 accumulators.
// ============================================================
__global__ __launch_bounds__(512) void attn_kernel(
    const float* __restrict__ tgt, const float* __restrict__ mem,
    const float* __restrict__ pos, const float* __restrict__ qpos,
    const int*   __restrict__ aidx)
{
    const int blk  = blockIdx.x;
    const int tid  = threadIdx.x;
    const int warp = tid >> 5, lane = tid & 31;
    const int q0   = blk * G;

    const int t0 = max(0, q0 - 1) * SEG;
    const int t1 = min(S, q0 + G + 1) * SEG;
    const int nf = t1 - t0;                      // 160 or 192

    __shared__ float4 qs[G][D / 4];
    __shared__ float  sp[G][3 * SEG];            // per-query 96-slot window
    __shared__ float  invd[G];

    // init score windows to -inf (edge slots may never be written)
    for (int i = tid; i < G * 3 * SEG; i += 512)
        ((float*)sp)[i] = -INFINITY;
    // q = tgt + query_pos (exactly one float4 per thread)
    {
        const int qi = tid >> 7, d4 = tid & 127;
        float4 tv = ((const float4*)tgt)[(size_t)(q0 + qi) * (D / 4) + d4];
        float4 pv = ((const float4*)qpos)[(size_t)(q0 + qi) * (D / 4) + d4];
        qs[qi][d4] = make_float4(tv.x + pv.x, tv.y + pv.y, tv.z + pv.z, tv.w + pv.w);
    }
    __syncthreads();

    const float scale = 0.04419417382415922f;  // 1/sqrt(512)

    // ---- scores: warp handles frame pair (base, base+16) ----
    for (int base = warp; base < nf; base += 32) {
        const int fA = base;
        const int fB = base + 16;
        const bool hasB = fB < nf;
        const int tA = t0 + fA;
        const int tB = t0 + (hasB ? fB : fA);
        const int aA = aidx[tA];
        const int aB = aidx[tB];
        const int rA = aA - 1 - q0;          // local query for e=0
        const int rB = aB - 1 - q0;
        // clamped smem rows (garbage dots for out-of-range e are not stored)
        const int qA0 = min(max(rA, 0), G - 1), qA1 = min(max(rA + 1, 0), G - 1), qA2 = min(max(rA + 2, 0), G - 1);
        const int qB0 = min(max(rB, 0), G - 1), qB1 = min(max(rB + 1, 0), G - 1), qB2 = min(max(rB + 2, 0), G - 1);

        const float4* mA = (const float4*)mem + (size_t)tA * (D / 4);
        const float4* pA = (const float4*)pos + (size_t)tA * (D / 4);
        const float4* mB = (const float4*)mem + (size_t)tB * (D / 4);
        const float4* pB = (const float4*)pos + (size_t)tB * (D / 4);

        float dA0 = 0.f, dA1 = 0.f, dA2 = 0.f;
        float dB0 = 0.f, dB1 = 0.f, dB2 = 0.f;
        #pragma unroll
        for (int i = 0; i < 4; i++) {
            const int d4 = lane + 32 * i;
            float4 ma = mA[d4], pa = pA[d4];
            float4 mb = mB[d4], pb = pB[d4];
            float4 kA = make_float4(ma.x + pa.x, ma.y + pa.y, ma.z + pa.z, ma.w + pa.w);
            float4 kB = make_float4(mb.x + pb.x, mb.y + pb.y, mb.z + pb.z, mb.w + pb.w);
            dA0 += dot4(kA, qs[qA0][d4]);
            dA1 += dot4(kA, qs[qA1][d4]);
            dA2 += dot4(kA, qs[qA2][d4]);
            dB0 += dot4(kB, qs[qB0][d4]);
            dB1 += dot4(kB, qs[qB1][d4]);
            dB2 += dot4(kB, qs[qB2][d4]);
        }
        #pragma unroll
        for (int o = 16; o > 0; o >>= 1) {
            dA0 += __shfl_xor_sync(0xffffffffu, dA0, o);
            dA1 += __shfl_xor_sync(0xffffffffu, dA1, o);
            dA2 += __shfl_xor_sync(0xffffffffu, dA2, o);
            dB0 += __shfl_xor_sync(0xffffffffu, dB0, o);
            dB1 += __shfl_xor_sync(0xffffffffu, dB1, o);
            dB2 += __shfl_xor_sync(0xffffffffu, dB2, o);
        }
        if (lane == 0) {
            const int u = tA & (SEG - 1);
            if (rA >= 0     && rA < G)     sp[rA][u + 64]     = dA0 * scale;
            if (rA + 1 >= 0 && rA + 1 < G) sp[rA + 1][u + 32] = dA1 * scale;
            if (rA + 2 >= 0 && rA + 2 < G) sp[rA + 2][u]      = dA2 * scale;
        } else if (lane == 1 && hasB) {
            const int u = tB & (SEG - 1);
            if (rB >= 0     && rB < G)     sp[rB][u + 64]     = dB0 * scale;
            if (rB + 1 >= 0 && rB + 1 < G) sp[rB + 1][u + 32] = dB1 * scale;
            if (rB + 2 >= 0 && rB + 2 < G) sp[rB + 2][u]      = dB2 * scale;
        }
    }
    __syncthreads();

    // ---- softmax: warp qi handles query qi (96 slots = 3/lane) ----
    if (warp < G) {
        const int qi = warp;
        float v0 = sp[qi][lane];
        float v1 = sp[qi][lane + 32];
        float v2 = sp[qi][lane + 64];
        float m = fmaxf(v0, fmaxf(v1, v2));
        #pragma unroll
        for (int o = 16; o > 0; o >>= 1)
            m = fmaxf(m, __shfl_xor_sync(0xffffffffu, m, o));
        float e0 = __expf(v0 - m);     // exp(-inf) = 0 for unwritten slots
        float e1 = __expf(v1 - m);
        float e2 = __expf(v2 - m);
        float ssum = e0 + e1 + e2;
        #pragma unroll
        for (int o = 16; o > 0; o >>= 1)
            ssum += __shfl_xor_sync(0xffffffffu, ssum, o);
        sp[qi][lane]      = e0;
        sp[qi][lane + 32] = e1;
        sp[qi][lane + 64] = e2;
        if (lane == 0) invd[qi] = 1.f / ssum;
    }
    __syncthreads();

    // ---- ctx: single pass over 6-seg union, 4 accumulators ----
    {
        const int dc = tid;                        // one float element
        float acc0 = 0.f, acc1 = 0.f, acc2 = 0.f, acc3 = 0.f;
        const int si_lo = (q0 == 0) ? 1 : 0;
        const int si_hi = min(6, 513 - q0);        // a = q0-1+si <= 511
        for (int si = si_lo; si < si_hi; si++) {
            const int a = q0 - 1 + si;
            const float* mrow = mem + (size_t)a * SEG * D + dc;
            // query e active iff e <= si <= e+2
            const bool p0 = (si <= 2);
            const bool p1 = (si >= 1 && si <= 3);
            const bool p2 = (si >= 2 && si <= 4);
            const bool p3 = (si >= 3);
            #pragma unroll
            for (int uu = 0; uu < SEG; uu += 4) {
                float mv0 = mrow[(size_t)(uu + 0) * D];
                float mv1 = mrow[(size_t)(uu + 1) * D];
                float mv2 = mrow[(size_t)(uu + 2) * D];
                float mv3 = mrow[(size_t)(uu + 3) * D];
                if (p0) {
                    const float* w = &sp[0][si * 32 + uu];
                    acc0 = fmaf(w[0], mv0, acc0); acc0 = fmaf(w[1], mv1, acc0);
                    acc0 = fmaf(w[2], mv2, acc0); acc0 = fmaf(w[3], mv3, acc0);
                }
                if (p1) {
                    const float* w = &sp[1][(si - 1) * 32 + uu];
                    acc1 = fmaf(w[0], mv0, acc1); acc1 = fmaf(w[1], mv1, acc1);
                    acc1 = fmaf(w[2], mv2, acc1); acc1 = fmaf(w[3], mv3, acc1);
                }
                if (p2) {
                    const float* w = &sp[2][(si - 2) * 32 + uu];
                    acc2 = fmaf(w[0], mv0, acc2); acc2 = fmaf(w[1], mv1, acc2);
                    acc2 = fmaf(w[2], mv2, acc2); acc2 = fmaf(w[3], mv3, acc2);
                }
                if (p3) {
                    const float* w = &sp[3][(si - 3) * 32 + uu];
                    acc3 = fmaf(w[0], mv0, acc3); acc3 = fmaf(w[1], mv1, acc3);
                    acc3 = fmaf(w[2], mv2, acc3); acc3 = fmaf(w[3], mv3, acc3);
                }
            }
        }
        acc0 = fmaxf(acc0 * invd[0], 0.f);
        acc1 = fmaxf(acc1 * invd[1], 0.f);
        acc2 = fmaxf(acc2 * invd[2], 0.f);
        acc3 = fmaxf(acc3 * invd[3], 0.f);
        g_rctx_h[(size_t)(q0 + 0) * D + dc] = __float2half_rn(acc0);
        g_rctx_h[(size_t)(q0 + 1) * D + dc] = __float2half_rn(acc1);
        g_rctx_h[(size_t)(q0 + 2) * D + dc] = __float2half_rn(acc2);
        g_rctx_h[(size_t)(q0 + 3) * D + dc] = __float2half_rn(acc3);
    }
}

// ============================================================
// FP16 tensor-core GEMM, 3-stage cp.async pipeline, 256 threads.
// ============================================================
template <int BN, int KSPLIT, int MODE>
__global__ __launch_bounds__(256) void gemm_h(
    const __half* __restrict__ A, const __half* __restrict__ W,
    const float* __restrict__ bias, void* __restrict__ C,
    int M, int N, int K)
{
    constexpr int BM = 64, BK = 64;
    constexpr int NWN = BN / 32;
    constexpr int NWM = 8 / NWN;
    constexpr int WM  = BM / NWM;
    constexpr int TM  = WM / 16;
    constexpr int LDA = BK + 8;
    constexpr int LDC = BN + 4;

    __shared__ union SmemU {
        struct { __half A[3][BM][LDA]; __half B[3][BN][LDA]; } s;
        float Cs[BM][LDC];
    } sm;

    const int tid  = threadIdx.x;
    const int warp = tid >> 5;
    const int wm = warp / NWN, wn = warp % NWN;
    const int col0 = blockIdx.x * BN;
    const int row0 = blockIdx.y * BM;
    const int Kloc = K / KSPLIT;
    const int kbase = blockIdx.z * Kloc;

    wmma::fragment<wmma::accumulator, 16, 16, 16, float> acc[TM][2];
    #pragma unroll
    for (int i = 0; i < TM; i++)
        #pragma unroll
        for (int j = 0; j < 2; j++)
            wmma::fill_fragment(acc[i][j], 0.f);

    const int NIT = Kloc / BK;

    auto load_tile = [&](int it, int st) {
        const int k0 = kbase + it * BK;
        #pragma unroll
        for (int i = tid; i < BM * (BK / 8); i += 256) {
            int r = i >> 3, c = (i & 7) * 8;
            cp_async16(&sm.s.A[st][r][c], &A[(size_t)(row0 + r) * K + k0 + c]);
        }
        #pragma unroll
        for (int i = tid; i < BN * (BK / 8); i += 256) {
            int r = i >> 3, c = (i & 7) * 8;
            cp_async16(&sm.s.B[st][r][c], &W[(size_t)(col0 + r) * K + k0 + c]);
        }
    };

    load_tile(0, 0);
    cp_commit();
    if (NIT > 1) load_tile(1, 1);
    cp_commit();

    for (int it = 0; it < NIT; it++) {
        if (it + 2 < NIT) load_tile(it + 2, (it + 2) % 3);
        cp_commit();
        cp_wait2();
        __syncthreads();

        const int st = it % 3;
        #pragma unroll
        for (int kk = 0; kk < BK; kk += 16) {
            wmma::fragment<wmma::matrix_a, 16, 16, 16, __half, wmma::row_major> fa[TM];
            wmma::fragment<wmma::matrix_b, 16, 16, 16, __half, wmma::col_major> fb[2];
            #pragma unroll
            for (int i = 0; i < TM; i++)
                wmma::load_matrix_sync(fa[i], &sm.s.A[st][wm * WM + i * 16][kk], LDA);
            #pragma unroll
            for (int j = 0; j < 2; j++)
                wmma::load_matrix_sync(fb[j], &sm.s.B[st][wn * 32 + j * 16][kk], LDA);
            #pragma unroll
            for (int i = 0; i < TM; i++)
                #pragma unroll
                for (int j = 0; j < 2; j++)
                    wmma::mma_sync(acc[i][j], fa[i], fb[j], acc[i][j]);
        }
        __syncthreads();
    }

    #pragma unroll
    for (int i = 0; i < TM; i++)
        #pragma unroll
        for (int j = 0; j < 2; j++)
            wmma::store_matrix_sync(&sm.Cs[wm * WM + i * 16][wn * 32 + j * 16],
                                    acc[i][j], LDC, wmma::mem_row_major);
    __syncthreads();

    if (MODE == 0) {
        float* Co = (float*)C + (size_t)blockIdx.z * M * N;
        #pragma unroll
        for (int i = tid; i < BM * (BN / 4); i += 256) {
            int r = i / (BN / 4), c = (i % (BN / 4)) * 4;
            float4 v = *(float4*)&sm.Cs[r][c];
            *(float4*)&Co[(size_t)(row0 + r) * N + col0 + c] = v;
        }
    } else {
        __half* Co = (__half*)C;
        #pragma unroll
        for (int i = tid; i < BM * (BN / 4); i += 256) {
            int r = i / (BN / 4), c = (i % (BN / 4)) * 4;
            float4 v = *(float4*)&sm.Cs[r][c];
            float4 b4 = *(const float4*)&bias[col0 + c];
            v.x = fmaxf(v.x + b4.x, 0.f);
            v.y = fmaxf(v.y + b4.y, 0.f);
            v.z = fmaxf(v.z + b4.z, 0.f);
            v.w = fmaxf(v.w + b4.w, 0.f);
            __half2* o2 = (__half2*)&Co[(size_t)(row0 + r) * N + col0 + c];
            o2[0] = __floats2half2_rn(v.x, v.y);
            o2[1] = __floats2half2_rn(v.z, v.w);
        }
    }
}

// ============================================================
// LayerNorm: 4 rows per 512-thread block.
// ============================================================
template <int NP, bool WH>
__global__ __launch_bounds__(512) void ln_kernel(
    const float* __restrict__ parts,
    const float* __restrict__ bias, const float* __restrict__ res,
    const float* __restrict__ g, const float* __restrict__ be,
    float* __restrict__ out)
{
    const int tid = threadIdx.x;
    const int rgrp = tid >> 7;                 // 0..3: row within block
    const int lt   = tid & 127;                // float4 lane within row
    const int row  = blockIdx.x * 4 + rgrp;
    const int warp = tid >> 5, lane = tid & 31;
    const size_t base = (size_t)row * (D / 4);

    float4 v = ((const float4*)res)[base + lt];
    {
        float4 b4 = ((const float4*)bias)[lt];
        v.x += b4.x; v.y += b4.y; v.z += b4.z; v.w += b4.w;
    }
    #pragma unroll
    for (int k = 0; k < NP; k++) {
        float4 pv = ((const float4*)parts)[(size_t)k * S * (D / 4) + base + lt];
        v.x += pv.x; v.y += pv.y; v.z += pv.z; v.w += pv.w;
    }

    float s1 = v.x + v.y + v.z + v.w;
    float s2 = v.x * v.x + v.y * v.y + v.z * v.z + v.w * v.w;

    __shared__ float r1[16], r2[16];
    __shared__ float mu_s[4], rstd_s[4];
    #pragma unroll
    for (int o = 16; o > 0; o >>= 1) {
        s1 += __shfl_xor_sync(0xffffffffu, s1, o);
        s2 += __shfl_xor_sync(0xffffffffu, s2, o);
    }
    if (lane == 0) { r1[warp] = s1; r2[warp] = s2; }
    __syncthreads();
    if (lt == 0) {
        const int w0 = rgrp * 4;
        float t1 = r1[w0] + r1[w0 + 1] + r1[w0 + 2] + r1[w0 + 3];
        float t2 = r2[w0] + r2[w0 + 1] + r2[w0 + 2] + r2[w0 + 3];
        const float mu = t1 * (1.0f / D);
        float var = t2 * (1.0f / D) - mu * mu;
        mu_s[rgrp] = mu;
        rstd_s[rgrp] = rsqrtf(fmaxf(var, 0.f) + 1e-5f);
    }
    __syncthreads();
    const float mu = mu_s[rgrp], rstd = rstd_s[rgrp];

    float4 g4 = ((const float4*)g)[lt];
    float4 b4 = ((const float4*)be)[lt];
    float4 o4;
    o4.x = (v.x - mu) * rstd * g4.x + b4.x;
    o4.y = (v.y - mu) * rstd * g4.y + b4.y;
    o4.z = (v.z - mu) * rstd * g4.z + b4.z;
    o4.w = (v.w - mu) * rstd * g4.w + b4.w;
    ((float4*)out)[base + lt] = o4;
    if (WH) {
        __half2* xh2 = (__half2*)g_xh + base * 2 + lt * 2;
        xh2[0] = __floats2half2_rn(o4.x, o4.y);
        xh2[1] = __floats2half2_rn(o4.z, o4.w);
    }
}

// ============================================================
extern "C" void kernel_launch(void* const* d_in, const int* in_sizes, int n_in,
                              void* d_out, int out_size)
{
    const float* tgt  = (const float*)d_in[0];
    const float* mem  = (const float*)d_in[1];
    const float* pos  = (const float*)d_in[2];
    const float* qpos = (const float*)d_in[3];
    const int*   aidx = (const int*)d_in[4];
    const float* Wt2  = (const float*)d_in[5];
    const float* bt2  = (const float*)d_in[6];
    const float* W1   = (const float*)d_in[7];
    const float* b1   = (const float*)d_in[8];
    const float* W2   = (const float*)d_in[9];
    const float* b2   = (const float*)d_in[10];
    const float* g2   = (const float*)d_in[11];
    const float* be2  = (const float*)d_in[12];
    const float* g3   = (const float*)d_in[13];
    const float* be3  = (const float*)d_in[14];
    float* out = (float*)d_out;

    __half *rctx_p, *xh_p, *h_p, *wh_p;
    float *x_p, *part_p;
    cudaGetSymbolAddress((void**)&rctx_p, g_rctx_h);
    cudaGetSymbolAddress((void**)&xh_p,   g_xh);
    cudaGetSymbolAddress((void**)&h_p,    g_h);
    cudaGetSymbolAddress((void**)&wh_p,   g_wh);
    cudaGetSymbolAddress((void**)&x_p,    g_x);
    cudaGetSymbolAddress((void**)&part_p, g_part);

    const __half* whT2 = wh_p;
    const __half* wh1  = wh_p + D * D;
    const __half* wh2  = wh_p + D * D + (size_t)DFF * D;

    // 0) weights fp32 -> fp16
    cvt_kernel<<<dim3(128, 3), 256>>>(Wt2, W1, W2);

    // 1) attention -> relu(ctx) fp16
    attn_kernel<<<S / G, 512>>>(tgt, mem, pos, qpos, aidx);

    // 2) tgt2 partials = rctx @ Wt2^T   [512,512,K=512], splitK=2
    gemm_h<64, 2, 0><<<dim3(D / 64, S / 64, 2), 256>>>(rctx_p, whT2, nullptr, part_p, S, D, D);

    // 3) x = LN(tgt + p0 + p1 + bt2); also fp16 x
    ln_kernel<2, true><<<S / 4, 512>>>(part_p, bt2, tgt, g2, be2, x_p);

    // 4) h = relu(x @ W1^T + b1) fp16   [512,2048,K=512]
    gemm_h<128, 1, 1><<<dim3(DFF / 128, S / 64, 1), 256>>>(xh_p, wh1, b1, h_p, S, DFF, D);

    // 5) ffn partials = h @ W2^T   [512,512,K=2048], splitK=2
    gemm_h<64, 2, 0><<<dim3(D / 64, S / 64, 2), 256>>>(h_p, wh2, nullptr, part_p, S, D, DFF);

    // 6) out = LN(x + p0 + p1 + b2)
    ln_kernel<2, false><<<S / 4, 512>>>(part_p, b2, x_p, g3, be3, out);
}